// round 14
// baseline (speedup 1.0000x reference)
#include <cuda_runtime.h>
#include <cuda_fp16.h>
#include <mma.h>
#include <cstdint>
#include <cstddef>

using namespace nvcuda;

#define BATCH 8
#define NQ    1500
#define DIM   256
#define MP1   1501
#define EROWS 1504        // padded row count per batch
#define ESTRIDE 1504      // E row stride (halves)
#define TSTRIDE 1536      // F2t row stride (halves)
#define MROWS 24000       // merged: 2 * BATCH * NQ
#define ITERS_RUN 14      // residual(14) ~ 2e-7, far below fp16 floor (1.4e-4)
#define CPB   16          // CTAs per batch for sinkhorn
#define RPC   (EROWS / CPB)   // 94 rows per CTA
#define COLSCALE 4194304.0f   // 2^22, fp16 underflow guard for x-vector

// ---------------- static device scratch ----------------
__device__ __half g_W1h[512 * 256];
__device__ __half g_W2h[256 * 256];
__device__ __half g_W3h[256 * 256];
__device__ __half g_tA[MROWS * 256];
__device__ __half g_tB[MROWS * 256];
__device__ __half g_F[MROWS * 256];       // rows [0,12000)=F1, [12000,24000)=F2
__device__ __half g_F2t[(size_t)BATCH * 256 * TSTRIDE];
__device__ __align__(16) __half g_E16[(size_t)BATCH * EROWS * ESTRIDE];
__device__ __align__(16) __half g_Et[(size_t)BATCH * EROWS * ESTRIDE];
__device__ __align__(16) float  g_x[BATCH * EROWS];
__device__ __align__(16) float  g_w[BATCH * EROWS];

// per-batch software barrier state (padded to separate cachelines)
struct __align__(128) BatchBar { unsigned count; unsigned gen; unsigned pad[30]; };
__device__ BatchBar g_bar[BATCH];

// ---------------- fast exp (FFMA only) ----------------
__device__ __forceinline__ float fast_exp(float x)
{
    float t = fmaf(x, 1.4426950408889634f, 12582912.0f);
    int   n = __float_as_int(t) - __float_as_int(12582912.0f);
    float r = t - 12582912.0f;
    float f = fmaf(-r, 0.6931471805599453f, x);
    float p = 1.3888889e-3f;
    p = fmaf(p, f, 8.3333333e-3f);
    p = fmaf(p, f, 4.1666667e-2f);
    p = fmaf(p, f, 1.6666667e-1f);
    p = fmaf(p, f, 5.0e-1f);
    p = fmaf(p, f, 1.0f);
    p = fmaf(p, f, 1.0f);
    return __int_as_float(__float_as_int(p) + (n << 23));
}

// 16 fp32 -> 16 fp16 (two uint4)
__device__ __forceinline__ void cvt16h(const float4 f[4], uint4& o0, uint4& o1)
{
    __half2 h0 = __floats2half2_rn(f[0].x, f[0].y);
    __half2 h1 = __floats2half2_rn(f[0].z, f[0].w);
    __half2 h2 = __floats2half2_rn(f[1].x, f[1].y);
    __half2 h3 = __floats2half2_rn(f[1].z, f[1].w);
    __half2 h4 = __floats2half2_rn(f[2].x, f[2].y);
    __half2 h5 = __floats2half2_rn(f[2].z, f[2].w);
    __half2 h6 = __floats2half2_rn(f[3].x, f[3].y);
    __half2 h7 = __floats2half2_rn(f[3].z, f[3].w);
    o0.x = *(unsigned*)&h0; o0.y = *(unsigned*)&h1;
    o0.z = *(unsigned*)&h2; o0.w = *(unsigned*)&h3;
    o1.x = *(unsigned*)&h4; o1.y = *(unsigned*)&h5;
    o1.z = *(unsigned*)&h6; o1.w = *(unsigned*)&h7;
}

// ---------------- prep kernels ----------------
__global__ void prep_weights(const float* __restrict__ W1,
                             const float* __restrict__ W2,
                             const float* __restrict__ W3)
{
    int i = blockIdx.x * 256 + threadIdx.x;
    if (i < 512 * 256) g_W1h[i] = __float2half(W1[i]);
    if (i < 256 * 256) {
        g_W2h[i] = __float2half(W2[i]);
        g_W3h[i] = __float2half(W3[i]);
    }
}

// ---------------- layer-1 GEMM: fused concat + fp32->fp16 convert in A-load ----------------
// C[M=24000, 256] = relu( concat(quer, pos)[row] @ W1 + b1 )
// rows < 12000 use pos_end, rows >= 12000 use pos_start (same quer).
__global__ __launch_bounds__(256, 2) void gemm16_l1(
    const float* __restrict__ quer, const float* __restrict__ pe,
    const float* __restrict__ ps,
    const __half* __restrict__ B, const float* __restrict__ bias,
    __half* __restrict__ C)
{
    const int K = 512;
    __shared__ __half As[128][40];
    __shared__ __half Bs[32][136];
    __shared__ __align__(32) float cbuf[8][16 * 20];

    int tid = threadIdx.x;
    int warp = tid >> 5, lane = tid & 31;
    int m0 = blockIdx.x * 128, n0 = blockIdx.y * 128;
    int wr = warp >> 2, wc = warp & 3;

    wmma::fragment<wmma::accumulator, 16, 16, 16, float> acc[4][2];
#pragma unroll
    for (int mi = 0; mi < 4; mi++)
#pragma unroll
        for (int ni = 0; ni < 2; ni++)
            wmma::fill_fragment(acc[mi][ni], 0.0f);

    int ar = tid >> 1, ac = (tid & 1) * 16;
    int br = tid >> 3, bc = (tid & 7) * 16;
    int gmA = m0 + ar;
    bool aok = gmA < MROWS;
    int srow = aok ? (gmA >= 12000 ? gmA - 12000 : gmA) : 0;
    const float* posP = (gmA >= 12000) ? ps : pe;

    float4 af[4];
    uint4 bv0, bv1;
    {
        // k0 = 0, cols ac..ac+15 all < 256 -> quer
        const float4* p = (const float4*)(quer + (size_t)srow * 256 + ac);
        if (aok) { af[0] = p[0]; af[1] = p[1]; af[2] = p[2]; af[3] = p[3]; }
        else { af[0] = af[1] = af[2] = af[3] = make_float4(0, 0, 0, 0); }
        const uint4* bp = (const uint4*)(B + (size_t)br * 256 + n0 + bc);
        bv0 = bp[0];
        bv1 = bp[1];
    }

    for (int k0 = 0; k0 < K; k0 += 32) {
        uint4 a0, a1;
        cvt16h(af, a0, a1);
        *(uint4*)&As[ar][ac] = a0;
        *(uint4*)&As[ar][ac + 8] = a1;
        *(uint4*)&Bs[br][bc] = bv0;
        *(uint4*)&Bs[br][bc + 8] = bv1;
        __syncthreads();

        if (k0 + 32 < K) {   // prefetch next tile
            int col = k0 + 32 + ac;
            const float* src = (col < 256) ? quer : posP;
            int cc = col & 255;
            const float4* p = (const float4*)(src + (size_t)srow * 256 + cc);
            if (aok) { af[0] = p[0]; af[1] = p[1]; af[2] = p[2]; af[3] = p[3]; }
            const uint4* bp = (const uint4*)(B + (size_t)(k0 + 32 + br) * 256 + n0 + bc);
            bv0 = bp[0];
            bv1 = bp[1];
        }

#pragma unroll
        for (int kk = 0; kk < 2; kk++) {
            wmma::fragment<wmma::matrix_b, 16, 16, 16, __half, wmma::row_major> bf[2];
#pragma unroll
            for (int ni = 0; ni < 2; ni++)
                wmma::load_matrix_sync(bf[ni], &Bs[kk * 16][wc * 32 + ni * 16], 136);
#pragma unroll
            for (int mi = 0; mi < 4; mi++) {
                wmma::fragment<wmma::matrix_a, 16, 16, 16, __half, wmma::row_major> afr;
                wmma::load_matrix_sync(afr, &As[wr * 64 + mi * 16][kk * 16], 40);
#pragma unroll
                for (int ni = 0; ni < 2; ni++)
                    wmma::mma_sync(acc[mi][ni], afr, bf[ni], acc[mi][ni]);
            }
        }
        __syncthreads();
    }

#pragma unroll
    for (int mi = 0; mi < 4; mi++)
#pragma unroll
        for (int ni = 0; ni < 2; ni++) {
            wmma::store_matrix_sync(&cbuf[warp][0], acc[mi][ni], 20, wmma::mem_row_major);
            __syncwarp();
#pragma unroll
            for (int q2 = 0; q2 < 8; q2++) {
                int idx = q2 * 32 + lane;
                int r = idx >> 4, c = idx & 15;
                int gm = m0 + wr * 64 + mi * 16 + r;
                int gn = n0 + wc * 32 + ni * 16 + c;
                if (gm < MROWS) {
                    float v = fmaxf(cbuf[warp][r * 20 + c] + bias[gn], 0.0f);
                    C[(size_t)gm * 256 + gn] = __float2half(v);
                }
            }
            __syncwarp();
        }
}

// ---------------- tensor-core GEMM (128x128 tile, 8 warps, reg-prefetch pipeline) ----------------
__global__ __launch_bounds__(256, 2) void gemm16(
    const __half* __restrict__ A, const __half* __restrict__ B,
    const float* __restrict__ bias, __half* __restrict__ C,
    int M, int K, int relu)
{
    __shared__ __half As[128][40];
    __shared__ __half Bs[32][136];
    __shared__ __align__(32) float cbuf[8][16 * 20];

    int tid = threadIdx.x;
    int warp = tid >> 5, lane = tid & 31;
    int m0 = blockIdx.x * 128, n0 = blockIdx.y * 128;
    int wr = warp >> 2, wc = warp & 3;

    wmma::fragment<wmma::accumulator, 16, 16, 16, float> acc[4][2];
#pragma unroll
    for (int mi = 0; mi < 4; mi++)
#pragma unroll
        for (int ni = 0; ni < 2; ni++)
            wmma::fill_fragment(acc[mi][ni], 0.0f);

    const uint4 zero4 = make_uint4(0, 0, 0, 0);

    int ar = tid >> 1, ac = (tid & 1) * 16;
    int br = tid >> 3, bc = (tid & 7) * 16;
    int gmA = m0 + ar;
    bool aok = gmA < M;

    uint4 av0, av1, bv0, bv1;
    {
        const uint4* ap = (const uint4*)(A + (size_t)gmA * K + ac);
        av0 = aok ? ap[0] : zero4;
        av1 = aok ? ap[1] : zero4;
        const uint4* bp = (const uint4*)(B + (size_t)br * 256 + n0 + bc);
        bv0 = bp[0];
        bv1 = bp[1];
    }

    for (int k0 = 0; k0 < K; k0 += 32) {
        *(uint4*)&As[ar][ac] = av0;
        *(uint4*)&As[ar][ac + 8] = av1;
        *(uint4*)&Bs[br][bc] = bv0;
        *(uint4*)&Bs[br][bc + 8] = bv1;
        __syncthreads();

        if (k0 + 32 < K) {
            const uint4* ap = (const uint4*)(A + (size_t)gmA * K + k0 + 32 + ac);
            av0 = aok ? ap[0] : zero4;
            av1 = aok ? ap[1] : zero4;
            const uint4* bp = (const uint4*)(B + (size_t)(k0 + 32 + br) * 256 + n0 + bc);
            bv0 = bp[0];
            bv1 = bp[1];
        }

#pragma unroll
        for (int kk = 0; kk < 2; kk++) {
            wmma::fragment<wmma::matrix_b, 16, 16, 16, __half, wmma::row_major> bf[2];
#pragma unroll
            for (int ni = 0; ni < 2; ni++)
                wmma::load_matrix_sync(bf[ni], &Bs[kk * 16][wc * 32 + ni * 16], 136);
#pragma unroll
            for (int mi = 0; mi < 4; mi++) {
                wmma::fragment<wmma::matrix_a, 16, 16, 16, __half, wmma::row_major> af;
                wmma::load_matrix_sync(af, &As[wr * 64 + mi * 16][kk * 16], 40);
#pragma unroll
                for (int ni = 0; ni < 2; ni++)
                    wmma::mma_sync(acc[mi][ni], af, bf[ni], acc[mi][ni]);
            }
        }
        __syncthreads();
    }

#pragma unroll
    for (int mi = 0; mi < 4; mi++)
#pragma unroll
        for (int ni = 0; ni < 2; ni++) {
            wmma::store_matrix_sync(&cbuf[warp][0], acc[mi][ni], 20, wmma::mem_row_major);
            __syncwarp();
#pragma unroll
            for (int q2 = 0; q2 < 8; q2++) {
                int idx = q2 * 32 + lane;
                int r = idx >> 4, c = idx & 15;
                int gm = m0 + wr * 64 + mi * 16 + r;
                int gn = n0 + wc * 32 + ni * 16 + c;
                if (gm < M) {
                    float v = cbuf[warp][r * 20 + c] + bias[gn];
                    if (relu) v = fmaxf(v, 0.0f);
                    C[(size_t)gm * 256 + gn] = __float2half(v);
                }
            }
            __syncwarp();
        }
}

// ---------------- transpose F2 [b][1500][256] -> F2t [b][256][TSTRIDE] ----------------
__global__ void transposeF2()
{
    __shared__ __half tile[32][33];
    int b = blockIdx.z;
    int i0 = blockIdx.x * 32, c0 = blockIdx.y * 32;
    const __half* F2 = g_F + (size_t)12000 * 256;
    for (int r = threadIdx.y; r < 32; r += 8) {
        int i = i0 + r;
        tile[r][threadIdx.x] = (i < NQ)
            ? F2[((size_t)b * NQ + i) * 256 + c0 + threadIdx.x]
            : __float2half(0.0f);
    }
    __syncthreads();
    for (int r = threadIdx.y; r < 32; r += 8) {
        int c = c0 + r;
        g_F2t[((size_t)b * 256 + c) * TSTRIDE + i0 + threadIdx.x] = tile[threadIdx.x][r];
    }
}

// ---------------- scores GEMM + E = exp(scores/16) + fused Et write ----------------
__global__ __launch_bounds__(256, 2) void scores16()
{
    __shared__ __half As[128][40];
    __shared__ __half Bs[32][136];
    __shared__ __align__(32) float cbuf[8][16 * 20];

    int b = blockIdx.z;
    int tid = threadIdx.x;
    int warp = tid >> 5, lane = tid & 31;
    int m0 = blockIdx.x * 128, n0 = blockIdx.y * 128;
    int wr = warp >> 2, wc = warp & 3;

    const __half* A  = g_F + (size_t)b * NQ * 256;
    const __half* Bt = g_F2t + (size_t)b * 256 * TSTRIDE;

    wmma::fragment<wmma::accumulator, 16, 16, 16, float> acc[4][2];
#pragma unroll
    for (int mi = 0; mi < 4; mi++)
#pragma unroll
        for (int ni = 0; ni < 2; ni++)
            wmma::fill_fragment(acc[mi][ni], 0.0f);

    const uint4 zero4 = make_uint4(0, 0, 0, 0);

    int ar = tid >> 1, ac = (tid & 1) * 16;
    int br = tid >> 3, bc = (tid & 7) * 16;
    int gmA = m0 + ar;
    bool aok = gmA < NQ;

    uint4 av0, av1, bv0, bv1;
    {
        const uint4* ap = (const uint4*)(A + (size_t)gmA * 256 + ac);
        av0 = aok ? ap[0] : zero4;
        av1 = aok ? ap[1] : zero4;
        const uint4* bp = (const uint4*)(Bt + (size_t)br * TSTRIDE + n0 + bc);
        bv0 = bp[0];
        bv1 = bp[1];
    }

    for (int k0 = 0; k0 < 256; k0 += 32) {
        *(uint4*)&As[ar][ac] = av0;
        *(uint4*)&As[ar][ac + 8] = av1;
        *(uint4*)&Bs[br][bc] = bv0;
        *(uint4*)&Bs[br][bc + 8] = bv1;
        __syncthreads();

        if (k0 + 32 < 256) {
            const uint4* ap = (const uint4*)(A + (size_t)gmA * 256 + k0 + 32 + ac);
            av0 = aok ? ap[0] : zero4;
            av1 = aok ? ap[1] : zero4;
            const uint4* bp = (const uint4*)(Bt + (size_t)(k0 + 32 + br) * TSTRIDE + n0 + bc);
            bv0 = bp[0];
            bv1 = bp[1];
        }

#pragma unroll
        for (int kk = 0; kk < 2; kk++) {
            wmma::fragment<wmma::matrix_b, 16, 16, 16, __half, wmma::row_major> bf[2];
#pragma unroll
            for (int ni = 0; ni < 2; ni++)
                wmma::load_matrix_sync(bf[ni], &Bs[kk * 16][wc * 32 + ni * 16], 136);
#pragma unroll
            for (int mi = 0; mi < 4; mi++) {
                wmma::fragment<wmma::matrix_a, 16, 16, 16, __half, wmma::row_major> af;
                wmma::load_matrix_sync(af, &As[wr * 64 + mi * 16][kk * 16], 40);
#pragma unroll
                for (int ni = 0; ni < 2; ni++)
                    wmma::mma_sync(acc[mi][ni], af, bf[ni], acc[mi][ni]);
            }
        }
        __syncthreads();
    }

#pragma unroll
    for (int mi = 0; mi < 4; mi++)
#pragma unroll
        for (int ni = 0; ni < 2; ni++) {
            wmma::store_matrix_sync(&cbuf[warp][0], acc[mi][ni], 20, wmma::mem_row_major);
            __syncwarp();
            // pass 1: exp in place + coalesced E writes (row-major)
#pragma unroll
            for (int q2 = 0; q2 < 8; q2++) {
                int idx = q2 * 32 + lane;
                int r = idx >> 4, c = idx & 15;
                int i = m0 + wr * 64 + mi * 16 + r;
                int j = n0 + wc * 32 + ni * 16 + c;
                float e = (i == j) ? 0.0f : fast_exp(cbuf[warp][r * 20 + c] * 0.0625f);
                cbuf[warp][r * 20 + c] = e;
                if (i < NQ && j < NQ)
                    g_E16[((size_t)(b * EROWS + i)) * ESTRIDE + j] = __float2half(e);
            }
            __syncwarp();
            // pass 2: transposed read of cbuf -> coalesced Et writes (Et[j][i])
#pragma unroll
            for (int q2 = 0; q2 < 8; q2++) {
                int idx = q2 * 32 + lane;
                int r2 = idx >> 4, c2 = idx & 15;   // r2: j-local, c2: i-local
                int i = m0 + wr * 64 + mi * 16 + c2;
                int j = n0 + wc * 32 + ni * 16 + r2;
                if (i < NQ && j < NQ)
                    g_Et[((size_t)(b * EROWS + j)) * ESTRIDE + i] =
                        __float2half(cbuf[warp][c2 * 20 + r2]);
            }
            __syncwarp();
        }
}

// bins + padding on BOTH E and Et: row/col 1500 = exp(alpha); rows/cols 1501..1503 = 0
__global__ void fill_bins(const float* __restrict__ binS)
{
    float ea = fast_exp(*binS);
    __half h = __float2half(ea);
    __half z = __float2half(0.0f);
    int b = blockIdx.y;
    int idx = blockIdx.x * 256 + threadIdx.x;
    if (idx < 1504) {
        __half v1500 = (idx <= 1500) ? h : z;
        g_E16[((size_t)(b * EROWS + 1500)) * ESTRIDE + idx] = v1500;
        g_Et [((size_t)(b * EROWS + 1500)) * ESTRIDE + idx] = v1500;
#pragma unroll
        for (int pr = 1501; pr <= 1503; pr++) {
            g_E16[((size_t)(b * EROWS + pr)) * ESTRIDE + idx] = z;
            g_Et [((size_t)(b * EROWS + pr)) * ESTRIDE + idx] = z;
        }
        if (idx < 1500) {
            g_E16[((size_t)(b * EROWS + idx)) * ESTRIDE + 1500] = h;
            g_Et [((size_t)(b * EROWS + idx)) * ESTRIDE + 1500] = h;
        }
        if (idx <= 1500) {
            __half* row  = g_E16 + ((size_t)(b * EROWS + idx)) * ESTRIDE;
            __half* rowt = g_Et  + ((size_t)(b * EROWS + idx)) * ESTRIDE;
            row[1501] = z; row[1502] = z; row[1503] = z;
            rowt[1501] = z; rowt[1502] = z; rowt[1503] = z;
        }
    }
}

// ---------------- persistent Sinkhorn: 128 CTAs, software per-batch barrier ----------------
__device__ __forceinline__ void batch_barrier(BatchBar* bar, int tid)
{
    __syncthreads();
    __threadfence();
    if (tid == 0) {
        unsigned old = *(volatile unsigned*)&bar->gen;
        unsigned prev = atomicAdd(&bar->count, 1u);
        if (prev == CPB - 1) {
            bar->count = 0;
            __threadfence();
            atomicExch(&bar->gen, old + 1u);
        } else {
            while (*(volatile unsigned*)&bar->gen == old) __nanosleep(64);
        }
        __threadfence();
    }
    __syncthreads();
}

// One warp sweeps up to 6 consecutive rows; HFMA2 inner products, fp32 per-chunk
// accumulation, double-buffered uint4 loads.
__device__ __forceinline__ void sweep6h(
    const __half* __restrict__ Ebase, const __half2* __restrict__ vech,
    float* __restrict__ outv, int ibase, int nrows, int lane, float scaleMul)
{
    float acc[6] = {0.f, 0.f, 0.f, 0.f, 0.f, 0.f};
    const __half* base = Ebase + (size_t)ibase * ESTRIDE;

    if (nrows == 6) {
        uint4 cur[6];
        int c = lane;
#pragma unroll
        for (int r = 0; r < 6; r++)
            cur[r] = *(const uint4*)(base + (size_t)r * ESTRIDE + c * 8);
        for (;;) {
            int cn = c + 32;
            bool has = (cn < 188);
            uint4 nxt[6];
            if (has) {
#pragma unroll
                for (int r = 0; r < 6; r++)
                    nxt[r] = *(const uint4*)(base + (size_t)r * ESTRIDE + cn * 8);
            }
            uint4 wv = *(const uint4*)&vech[c * 4];
            __half2 w01 = *(const __half2*)&wv.x;
            __half2 w23 = *(const __half2*)&wv.y;
            __half2 w45 = *(const __half2*)&wv.z;
            __half2 w67 = *(const __half2*)&wv.w;
#pragma unroll
            for (int r = 0; r < 6; r++) {
                __half2 p = __hmul2(*(const __half2*)&cur[r].x, w01);
                p = __hfma2(*(const __half2*)&cur[r].y, w23, p);
                p = __hfma2(*(const __half2*)&cur[r].z, w45, p);
                p = __hfma2(*(const __half2*)&cur[r].w, w67, p);
                float2 pf = __half22float2(p);
                acc[r] += pf.x + pf.y;
            }
            if (!has) break;
#pragma unroll
            for (int r = 0; r < 6; r++) cur[r] = nxt[r];
            c = cn;
        }
    } else {
        for (int c = lane; c < 188; c += 32) {
            uint4 wv = *(const uint4*)&vech[c * 4];
            __half2 w01 = *(const __half2*)&wv.x;
            __half2 w23 = *(const __half2*)&wv.y;
            __half2 w45 = *(const __half2*)&wv.z;
            __half2 w67 = *(const __half2*)&wv.w;
            const __half* p0 = base + c * 8;
            for (int r = 0; r < nrows; r++) {
                uint4 ev = *(const uint4*)(p0 + (size_t)r * ESTRIDE);
                __half2 p = __hmul2(*(const __half2*)&ev.x, w01);
                p = __hfma2(*(const __half2*)&ev.y, w23, p);
                p = __hfma2(*(const __half2*)&ev.z, w45, p);
                p = __hfma2(*(const __half2*)&ev.w, w67, p);
                float2 pf = __half22float2(p);
                acc[r] += pf.x + pf.y;
            }
        }
    }

#pragma unroll
    for (int r = 0; r < 6; r++) {
        float s = acc[r];
#pragma unroll
        for (int o = 16; o; o >>= 1) s += __shfl_xor_sync(0xffffffffu, s, o);
        if (lane == 0 && r < nrows) {
            int i = ibase + r;
            float m = (i < 1500) ? (1.0f / 3000.0f) : 0.5f;
            __stcg(&outv[i], m * scaleMul / s);   // pad rows -> inf, never consumed
        }
    }
}

__global__ void __launch_bounds__(512) sinkhorn_pers()
{
    int b = blockIdx.x / CPB;
    int rank = blockIdx.x % CPB;
    int r0 = rank * RPC;
    int tid = threadIdx.x;
    int warp = tid >> 5, lane = tid & 31;

    int ibase = r0 + warp * 6;
    int nrows = max(0, min(6, r0 + RPC - ibase));   // warp 15 -> 4 rows

    __shared__ __align__(16) __half2 vech[752];

    const __half* Eb  = g_E16 + (size_t)b * EROWS * ESTRIDE;
    const __half* Etb = g_Et  + (size_t)b * EROWS * ESTRIDE;
    float* xb = g_x + b * EROWS;
    float* wb = g_w + b * EROWS;
    BatchBar* bar = &g_bar[b];

    if (tid < RPC) __stcg(&wb[r0 + tid], 1.0f);
    batch_barrier(bar, tid);

#pragma unroll 1
    for (int it = 0; it < ITERS_RUN; it++) {
        // ---- row phase: x = mu / (E w); w vector in half, scale 1 ----
        for (int t = tid; t < 752; t += 512) {
            int j = t * 2;
            float a = (j < MP1) ? __ldcg(&wb[j]) : 0.0f;
            float bb = (j + 1 < MP1) ? __ldcg(&wb[j + 1]) : 0.0f;
            vech[t] = __floats2half2_rn(a, bb);
        }
        __syncthreads();
        if (nrows > 0) sweep6h(Eb, vech, xb, ibase, nrows, lane, 1.0f);
        batch_barrier(bar, tid);

        // ---- col phase: w = nu / (Et x); x scaled by 2^22 for fp16 range ----
        for (int t = tid; t < 752; t += 512) {
            int j = t * 2;
            float a = (j < MP1) ? __ldcg(&xb[j]) * COLSCALE : 0.0f;
            float bb = (j + 1 < MP1) ? __ldcg(&xb[j + 1]) * COLSCALE : 0.0f;
            vech[t] = __floats2half2_rn(a, bb);
        }
        __syncthreads();
        if (nrows > 0) sweep6h(Etb, vech, wb, ibase, nrows, lane, COLSCALE);
        batch_barrier(bar, tid);
    }
}

// ---------------- final: out = E * x_i * w_j * 3000 ----------------
// grid (1501, 8), block 376; each thread handles 4 consecutive j
__global__ __launch_bounds__(384) void final_out(float* __restrict__ out)
{
    int i = blockIdx.x;
    int b = blockIdx.y;
    int j0 = threadIdx.x * 4;
    float xi = g_x[b * EROWS + i] * 3000.0f;
    const __half* erow = g_E16 + ((size_t)(b * EROWS + i)) * ESTRIDE;
    uint2 ev = *(const uint2*)(erow + j0);
    float4 wv = *(const float4*)&g_w[b * EROWS + j0];
    float2 e01 = __half22float2(*(const __half2*)&ev.x);
    float2 e23 = __half22float2(*(const __half2*)&ev.y);
    float* orow = out + ((size_t)(b * MP1 + i)) * 1501;
    float r0 = e01.x * xi * wv.x;
    float r1 = e01.y * xi * wv.y;
    float r2 = e23.x * xi * wv.z;
    float r3 = e23.y * xi * wv.w;
    if (j0 + 3 <= 1500) {
        orow[j0] = r0; orow[j0 + 1] = r1; orow[j0 + 2] = r2; orow[j0 + 3] = r3;
    } else {
        if (j0 <= 1500) orow[j0] = r0;
        if (j0 + 1 <= 1500) orow[j0 + 1] = r1;
        if (j0 + 2 <= 1500) orow[j0 + 2] = r2;
    }
}

// ---------------- launch ----------------
extern "C" void kernel_launch(void* const* d_in, const int* in_sizes, int n_in,
                              void* d_out, int out_size)
{
    const float* quer      = (const float*)d_in[0];
    const float* pos_start = (const float*)d_in[1];
    const float* pos_end   = (const float*)d_in[2];
    const float* W1 = (const float*)d_in[3];
    const float* b1 = (const float*)d_in[4];
    const float* W2 = (const float*)d_in[5];
    const float* b2 = (const float*)d_in[6];
    const float* W3 = (const float*)d_in[7];
    const float* b3 = (const float*)d_in[8];
    const float* binS = (const float*)d_in[9];

    __half *W1h, *W2h, *W3h, *tA, *tB, *F;
    cudaGetSymbolAddress((void**)&W1h, g_W1h);
    cudaGetSymbolAddress((void**)&W2h, g_W2h);
    cudaGetSymbolAddress((void**)&W3h, g_W3h);
    cudaGetSymbolAddress((void**)&tA, g_tA);
    cudaGetSymbolAddress((void**)&tB, g_tB);
    cudaGetSymbolAddress((void**)&F, g_F);

    prep_weights<<<512, 256>>>(W1, W2, W3);

    dim3 gG(188, 2);  // ceil(24000/128) x 256/128
    gemm16_l1<<<gG, 256>>>(quer, pos_end, pos_start, W1h, b1, tA);
    gemm16<<<gG, 256>>>(tA, W2h, b2, tB, MROWS, 256, 1);
    gemm16<<<gG, 256>>>(tB, W3h, b3, F,  MROWS, 256, 0);

    transposeF2<<<dim3(48, 8, 8), dim3(32, 8)>>>();
    scores16<<<dim3(12, 12, 8), 256>>>();
    fill_bins<<<dim3(6, 8), 256>>>(binS);

    sinkhorn_pers<<<BATCH * CPB, 512>>>();

    final_out<<<dim3(1501, 8), 376>>>((float*)d_out);
}

// round 15
// speedup vs baseline: 1.0029x; 1.0029x over previous
#include <cuda_runtime.h>
#include <cuda_fp16.h>
#include <mma.h>
#include <cstdint>
#include <cstddef>

using namespace nvcuda;

#define BATCH 8
#define NQ    1500
#define DIM   256
#define MP1   1501
#define EROWS 1504        // padded row count per batch
#define ESTRIDE 1504      // E row stride (halves)
#define TSTRIDE 1536      // F2t row stride (halves)
#define MROWS 24000       // merged: 2 * BATCH * NQ
#define ITERS_RUN 14      // residual(14) ~ 2e-7, far below fp16 floor (1.4e-4)
#define CPB   16          // CTAs per batch for sinkhorn
#define RPC   (EROWS / CPB)   // 94 rows per CTA
#define COLSCALE 4194304.0f   // 2^22, fp16 underflow guard for x-vector

// ---------------- static device scratch ----------------
__device__ __half g_W1h[512 * 256];
__device__ __half g_W2h[256 * 256];
__device__ __half g_W3h[256 * 256];
__device__ __half g_tA[MROWS * 256];
__device__ __half g_tB[MROWS * 256];
__device__ __half g_F[MROWS * 256];       // rows [0,12000)=F1, [12000,24000)=F2
__device__ __half g_F2t[(size_t)BATCH * 256 * TSTRIDE];
__device__ __align__(16) __half g_E16[(size_t)BATCH * EROWS * ESTRIDE];
__device__ __align__(16) __half g_Et[(size_t)BATCH * EROWS * ESTRIDE];
__device__ __align__(16) float  g_x[BATCH * EROWS];
__device__ __align__(16) float  g_w[BATCH * EROWS];

// per-batch software barrier state (padded to separate cachelines)
struct __align__(128) BatchBar { unsigned count; unsigned gen; unsigned pad[30]; };
__device__ BatchBar g_bar[BATCH];

// ---------------- fast exp (FFMA only) ----------------
__device__ __forceinline__ float fast_exp(float x)
{
    float t = fmaf(x, 1.4426950408889634f, 12582912.0f);
    int   n = __float_as_int(t) - __float_as_int(12582912.0f);
    float r = t - 12582912.0f;
    float f = fmaf(-r, 0.6931471805599453f, x);
    float p = 1.3888889e-3f;
    p = fmaf(p, f, 8.3333333e-3f);
    p = fmaf(p, f, 4.1666667e-2f);
    p = fmaf(p, f, 1.6666667e-1f);
    p = fmaf(p, f, 5.0e-1f);
    p = fmaf(p, f, 1.0f);
    p = fmaf(p, f, 1.0f);
    return __int_as_float(__float_as_int(p) + (n << 23));
}

// 16 fp32 -> 16 fp16 (two uint4)
__device__ __forceinline__ void cvt16h(const float4 f[4], uint4& o0, uint4& o1)
{
    __half2 h0 = __floats2half2_rn(f[0].x, f[0].y);
    __half2 h1 = __floats2half2_rn(f[0].z, f[0].w);
    __half2 h2 = __floats2half2_rn(f[1].x, f[1].y);
    __half2 h3 = __floats2half2_rn(f[1].z, f[1].w);
    __half2 h4 = __floats2half2_rn(f[2].x, f[2].y);
    __half2 h5 = __floats2half2_rn(f[2].z, f[2].w);
    __half2 h6 = __floats2half2_rn(f[3].x, f[3].y);
    __half2 h7 = __floats2half2_rn(f[3].z, f[3].w);
    o0.x = *(unsigned*)&h0; o0.y = *(unsigned*)&h1;
    o0.z = *(unsigned*)&h2; o0.w = *(unsigned*)&h3;
    o1.x = *(unsigned*)&h4; o1.y = *(unsigned*)&h5;
    o1.z = *(unsigned*)&h6; o1.w = *(unsigned*)&h7;
}

// ---------------- prep kernels ----------------
__global__ void prep_weights(const float* __restrict__ W1,
                             const float* __restrict__ W2,
                             const float* __restrict__ W3)
{
    int i = blockIdx.x * 256 + threadIdx.x;
    if (i < 512 * 256) g_W1h[i] = __float2half(W1[i]);
    if (i < 256 * 256) {
        g_W2h[i] = __float2half(W2[i]);
        g_W3h[i] = __float2half(W3[i]);
    }
}

// ---------------- layer-1 GEMM: fused concat + fp32->fp16 convert in A-load ----------------
// C[M=24000, 256] = relu( concat(quer, pos)[row] @ W1 + b1 )
// rows < 12000 use pos_end, rows >= 12000 use pos_start (same quer).
__global__ __launch_bounds__(256, 2) void gemm16_l1(
    const float* __restrict__ quer, const float* __restrict__ pe,
    const float* __restrict__ ps,
    const __half* __restrict__ B, const float* __restrict__ bias,
    __half* __restrict__ C)
{
    const int K = 512;
    __shared__ __half As[128][40];
    __shared__ __half Bs[32][136];
    __shared__ __align__(32) float cbuf[8][16 * 20];

    int tid = threadIdx.x;
    int warp = tid >> 5, lane = tid & 31;
    int m0 = blockIdx.x * 128, n0 = blockIdx.y * 128;
    int wr = warp >> 2, wc = warp & 3;

    wmma::fragment<wmma::accumulator, 16, 16, 16, float> acc[4][2];
#pragma unroll
    for (int mi = 0; mi < 4; mi++)
#pragma unroll
        for (int ni = 0; ni < 2; ni++)
            wmma::fill_fragment(acc[mi][ni], 0.0f);

    int ar = tid >> 1, ac = (tid & 1) * 16;
    int br = tid >> 3, bc = (tid & 7) * 16;
    int gmA = m0 + ar;
    bool aok = gmA < MROWS;
    int srow = aok ? (gmA >= 12000 ? gmA - 12000 : gmA) : 0;
    const float* posP = (gmA >= 12000) ? ps : pe;

    float4 af[4];
    uint4 bv0, bv1;
    {
        // k0 = 0, cols ac..ac+15 all < 256 -> quer
        const float4* p = (const float4*)(quer + (size_t)srow * 256 + ac);
        if (aok) { af[0] = p[0]; af[1] = p[1]; af[2] = p[2]; af[3] = p[3]; }
        else { af[0] = af[1] = af[2] = af[3] = make_float4(0, 0, 0, 0); }
        const uint4* bp = (const uint4*)(B + (size_t)br * 256 + n0 + bc);
        bv0 = bp[0];
        bv1 = bp[1];
    }

    for (int k0 = 0; k0 < K; k0 += 32) {
        uint4 a0, a1;
        cvt16h(af, a0, a1);
        *(uint4*)&As[ar][ac] = a0;
        *(uint4*)&As[ar][ac + 8] = a1;
        *(uint4*)&Bs[br][bc] = bv0;
        *(uint4*)&Bs[br][bc + 8] = bv1;
        __syncthreads();

        if (k0 + 32 < K) {   // prefetch next tile
            int col = k0 + 32 + ac;
            const float* src = (col < 256) ? quer : posP;
            int cc = col & 255;
            const float4* p = (const float4*)(src + (size_t)srow * 256 + cc);
            if (aok) { af[0] = p[0]; af[1] = p[1]; af[2] = p[2]; af[3] = p[3]; }
            const uint4* bp = (const uint4*)(B + (size_t)(k0 + 32 + br) * 256 + n0 + bc);
            bv0 = bp[0];
            bv1 = bp[1];
        }

#pragma unroll
        for (int kk = 0; kk < 2; kk++) {
            wmma::fragment<wmma::matrix_b, 16, 16, 16, __half, wmma::row_major> bf[2];
#pragma unroll
            for (int ni = 0; ni < 2; ni++)
                wmma::load_matrix_sync(bf[ni], &Bs[kk * 16][wc * 32 + ni * 16], 136);
#pragma unroll
            for (int mi = 0; mi < 4; mi++) {
                wmma::fragment<wmma::matrix_a, 16, 16, 16, __half, wmma::row_major> afr;
                wmma::load_matrix_sync(afr, &As[wr * 64 + mi * 16][kk * 16], 40);
#pragma unroll
                for (int ni = 0; ni < 2; ni++)
                    wmma::mma_sync(acc[mi][ni], afr, bf[ni], acc[mi][ni]);
            }
        }
        __syncthreads();
    }

#pragma unroll
    for (int mi = 0; mi < 4; mi++)
#pragma unroll
        for (int ni = 0; ni < 2; ni++) {
            wmma::store_matrix_sync(&cbuf[warp][0], acc[mi][ni], 20, wmma::mem_row_major);
            __syncwarp();
#pragma unroll
            for (int q2 = 0; q2 < 8; q2++) {
                int idx = q2 * 32 + lane;
                int r = idx >> 4, c = idx & 15;
                int gm = m0 + wr * 64 + mi * 16 + r;
                int gn = n0 + wc * 32 + ni * 16 + c;
                if (gm < MROWS) {
                    float v = fmaxf(cbuf[warp][r * 20 + c] + bias[gn], 0.0f);
                    C[(size_t)gm * 256 + gn] = __float2half(v);
                }
            }
            __syncwarp();
        }
}

// ---------------- tensor-core GEMM (128x128 tile, 8 warps, reg-prefetch pipeline) ----------------
__global__ __launch_bounds__(256, 2) void gemm16(
    const __half* __restrict__ A, const __half* __restrict__ B,
    const float* __restrict__ bias, __half* __restrict__ C,
    int M, int K, int relu)
{
    __shared__ __half As[128][40];
    __shared__ __half Bs[32][136];
    __shared__ __align__(32) float cbuf[8][16 * 20];

    int tid = threadIdx.x;
    int warp = tid >> 5, lane = tid & 31;
    int m0 = blockIdx.x * 128, n0 = blockIdx.y * 128;
    int wr = warp >> 2, wc = warp & 3;

    wmma::fragment<wmma::accumulator, 16, 16, 16, float> acc[4][2];
#pragma unroll
    for (int mi = 0; mi < 4; mi++)
#pragma unroll
        for (int ni = 0; ni < 2; ni++)
            wmma::fill_fragment(acc[mi][ni], 0.0f);

    const uint4 zero4 = make_uint4(0, 0, 0, 0);

    int ar = tid >> 1, ac = (tid & 1) * 16;
    int br = tid >> 3, bc = (tid & 7) * 16;
    int gmA = m0 + ar;
    bool aok = gmA < M;

    uint4 av0, av1, bv0, bv1;
    {
        const uint4* ap = (const uint4*)(A + (size_t)gmA * K + ac);
        av0 = aok ? ap[0] : zero4;
        av1 = aok ? ap[1] : zero4;
        const uint4* bp = (const uint4*)(B + (size_t)br * 256 + n0 + bc);
        bv0 = bp[0];
        bv1 = bp[1];
    }

    for (int k0 = 0; k0 < K; k0 += 32) {
        *(uint4*)&As[ar][ac] = av0;
        *(uint4*)&As[ar][ac + 8] = av1;
        *(uint4*)&Bs[br][bc] = bv0;
        *(uint4*)&Bs[br][bc + 8] = bv1;
        __syncthreads();

        if (k0 + 32 < K) {
            const uint4* ap = (const uint4*)(A + (size_t)gmA * K + k0 + 32 + ac);
            av0 = aok ? ap[0] : zero4;
            av1 = aok ? ap[1] : zero4;
            const uint4* bp = (const uint4*)(B + (size_t)(k0 + 32 + br) * 256 + n0 + bc);
            bv0 = bp[0];
            bv1 = bp[1];
        }

#pragma unroll
        for (int kk = 0; kk < 2; kk++) {
            wmma::fragment<wmma::matrix_b, 16, 16, 16, __half, wmma::row_major> bf[2];
#pragma unroll
            for (int ni = 0; ni < 2; ni++)
                wmma::load_matrix_sync(bf[ni], &Bs[kk * 16][wc * 32 + ni * 16], 136);
#pragma unroll
            for (int mi = 0; mi < 4; mi++) {
                wmma::fragment<wmma::matrix_a, 16, 16, 16, __half, wmma::row_major> af;
                wmma::load_matrix_sync(af, &As[wr * 64 + mi * 16][kk * 16], 40);
#pragma unroll
                for (int ni = 0; ni < 2; ni++)
                    wmma::mma_sync(acc[mi][ni], af, bf[ni], acc[mi][ni]);
            }
        }
        __syncthreads();
    }

#pragma unroll
    for (int mi = 0; mi < 4; mi++)
#pragma unroll
        for (int ni = 0; ni < 2; ni++) {
            wmma::store_matrix_sync(&cbuf[warp][0], acc[mi][ni], 20, wmma::mem_row_major);
            __syncwarp();
#pragma unroll
            for (int q2 = 0; q2 < 8; q2++) {
                int idx = q2 * 32 + lane;
                int r = idx >> 4, c = idx & 15;
                int gm = m0 + wr * 64 + mi * 16 + r;
                int gn = n0 + wc * 32 + ni * 16 + c;
                if (gm < M) {
                    float v = cbuf[warp][r * 20 + c] + bias[gn];
                    if (relu) v = fmaxf(v, 0.0f);
                    C[(size_t)gm * 256 + gn] = __float2half(v);
                }
            }
            __syncwarp();
        }
}

// ---------------- transpose F2 [b][1500][256] -> F2t [b][256][TSTRIDE] ----------------
__global__ void transposeF2()
{
    __shared__ __half tile[32][33];
    int b = blockIdx.z;
    int i0 = blockIdx.x * 32, c0 = blockIdx.y * 32;
    const __half* F2 = g_F + (size_t)12000 * 256;
    for (int r = threadIdx.y; r < 32; r += 8) {
        int i = i0 + r;
        tile[r][threadIdx.x] = (i < NQ)
            ? F2[((size_t)b * NQ + i) * 256 + c0 + threadIdx.x]
            : __float2half(0.0f);
    }
    __syncthreads();
    for (int r = threadIdx.y; r < 32; r += 8) {
        int c = c0 + r;
        g_F2t[((size_t)b * 256 + c) * TSTRIDE + i0 + threadIdx.x] = tile[threadIdx.x][r];
    }
}

// ---------------- scores GEMM + E = exp(scores/16) + fused Et write ----------------
__global__ __launch_bounds__(256, 2) void scores16()
{
    __shared__ __half As[128][40];
    __shared__ __half Bs[32][136];
    __shared__ __align__(32) float cbuf[8][16 * 20];

    int b = blockIdx.z;
    int tid = threadIdx.x;
    int warp = tid >> 5, lane = tid & 31;
    int m0 = blockIdx.x * 128, n0 = blockIdx.y * 128;
    int wr = warp >> 2, wc = warp & 3;

    const __half* A  = g_F + (size_t)b * NQ * 256;
    const __half* Bt = g_F2t + (size_t)b * 256 * TSTRIDE;

    wmma::fragment<wmma::accumulator, 16, 16, 16, float> acc[4][2];
#pragma unroll
    for (int mi = 0; mi < 4; mi++)
#pragma unroll
        for (int ni = 0; ni < 2; ni++)
            wmma::fill_fragment(acc[mi][ni], 0.0f);

    const uint4 zero4 = make_uint4(0, 0, 0, 0);

    int ar = tid >> 1, ac = (tid & 1) * 16;
    int br = tid >> 3, bc = (tid & 7) * 16;
    int gmA = m0 + ar;
    bool aok = gmA < NQ;

    uint4 av0, av1, bv0, bv1;
    {
        const uint4* ap = (const uint4*)(A + (size_t)gmA * 256 + ac);
        av0 = aok ? ap[0] : zero4;
        av1 = aok ? ap[1] : zero4;
        const uint4* bp = (const uint4*)(Bt + (size_t)br * TSTRIDE + n0 + bc);
        bv0 = bp[0];
        bv1 = bp[1];
    }

    for (int k0 = 0; k0 < 256; k0 += 32) {
        *(uint4*)&As[ar][ac] = av0;
        *(uint4*)&As[ar][ac + 8] = av1;
        *(uint4*)&Bs[br][bc] = bv0;
        *(uint4*)&Bs[br][bc + 8] = bv1;
        __syncthreads();

        if (k0 + 32 < 256) {
            const uint4* ap = (const uint4*)(A + (size_t)gmA * 256 + k0 + 32 + ac);
            av0 = aok ? ap[0] : zero4;
            av1 = aok ? ap[1] : zero4;
            const uint4* bp = (const uint4*)(Bt + (size_t)(k0 + 32 + br) * TSTRIDE + n0 + bc);
            bv0 = bp[0];
            bv1 = bp[1];
        }

#pragma unroll
        for (int kk = 0; kk < 2; kk++) {
            wmma::fragment<wmma::matrix_b, 16, 16, 16, __half, wmma::row_major> bf[2];
#pragma unroll
            for (int ni = 0; ni < 2; ni++)
                wmma::load_matrix_sync(bf[ni], &Bs[kk * 16][wc * 32 + ni * 16], 136);
#pragma unroll
            for (int mi = 0; mi < 4; mi++) {
                wmma::fragment<wmma::matrix_a, 16, 16, 16, __half, wmma::row_major> af;
                wmma::load_matrix_sync(af, &As[wr * 64 + mi * 16][kk * 16], 40);
#pragma unroll
                for (int ni = 0; ni < 2; ni++)
                    wmma::mma_sync(acc[mi][ni], af, bf[ni], acc[mi][ni]);
            }
        }
        __syncthreads();
    }

#pragma unroll
    for (int mi = 0; mi < 4; mi++)
#pragma unroll
        for (int ni = 0; ni < 2; ni++) {
            wmma::store_matrix_sync(&cbuf[warp][0], acc[mi][ni], 20, wmma::mem_row_major);
            __syncwarp();
            // pass 1: exp in place + coalesced E writes (row-major)
#pragma unroll
            for (int q2 = 0; q2 < 8; q2++) {
                int idx = q2 * 32 + lane;
                int r = idx >> 4, c = idx & 15;
                int i = m0 + wr * 64 + mi * 16 + r;
                int j = n0 + wc * 32 + ni * 16 + c;
                float e = (i == j) ? 0.0f : fast_exp(cbuf[warp][r * 20 + c] * 0.0625f);
                cbuf[warp][r * 20 + c] = e;
                if (i < NQ && j < NQ)
                    g_E16[((size_t)(b * EROWS + i)) * ESTRIDE + j] = __float2half(e);
            }
            __syncwarp();
            // pass 2: transposed read of cbuf -> coalesced Et writes (Et[j][i])
#pragma unroll
            for (int q2 = 0; q2 < 8; q2++) {
                int idx = q2 * 32 + lane;
                int r2 = idx >> 4, c2 = idx & 15;   // r2: j-local, c2: i-local
                int i = m0 + wr * 64 + mi * 16 + c2;
                int j = n0 + wc * 32 + ni * 16 + r2;
                if (i < NQ && j < NQ)
                    g_Et[((size_t)(b * EROWS + j)) * ESTRIDE + i] =
                        __float2half(cbuf[warp][c2 * 20 + r2]);
            }
            __syncwarp();
        }
}

// bins + padding on BOTH E and Et: row/col 1500 = exp(alpha); rows/cols 1501..1503 = 0
__global__ void fill_bins(const float* __restrict__ binS)
{
    float ea = fast_exp(*binS);
    __half h = __float2half(ea);
    __half z = __float2half(0.0f);
    int b = blockIdx.y;
    int idx = blockIdx.x * 256 + threadIdx.x;
    if (idx < 1504) {
        __half v1500 = (idx <= 1500) ? h : z;
        g_E16[((size_t)(b * EROWS + 1500)) * ESTRIDE + idx] = v1500;
        g_Et [((size_t)(b * EROWS + 1500)) * ESTRIDE + idx] = v1500;
#pragma unroll
        for (int pr = 1501; pr <= 1503; pr++) {
            g_E16[((size_t)(b * EROWS + pr)) * ESTRIDE + idx] = z;
            g_Et [((size_t)(b * EROWS + pr)) * ESTRIDE + idx] = z;
        }
        if (idx < 1500) {
            g_E16[((size_t)(b * EROWS + idx)) * ESTRIDE + 1500] = h;
            g_Et [((size_t)(b * EROWS + idx)) * ESTRIDE + 1500] = h;
        }
        if (idx <= 1500) {
            __half* row  = g_E16 + ((size_t)(b * EROWS + idx)) * ESTRIDE;
            __half* rowt = g_Et  + ((size_t)(b * EROWS + idx)) * ESTRIDE;
            row[1501] = z; row[1502] = z; row[1503] = z;
            rowt[1501] = z; rowt[1502] = z; rowt[1503] = z;
        }
    }
}

// ---------------- persistent Sinkhorn: 128 CTAs, software per-batch barrier ----------------
__device__ __forceinline__ void batch_barrier(BatchBar* bar, int tid)
{
    __syncthreads();
    __threadfence();
    if (tid == 0) {
        unsigned old = *(volatile unsigned*)&bar->gen;
        unsigned prev = atomicAdd(&bar->count, 1u);
        if (prev == CPB - 1) {
            bar->count = 0;
            __threadfence();
            atomicExch(&bar->gen, old + 1u);
        } else {
            while (*(volatile unsigned*)&bar->gen == old) __nanosleep(64);
        }
        __threadfence();
    }
    __syncthreads();
}

// One warp sweeps up to 6 consecutive rows; HFMA2 inner products, fp32 per-chunk
// accumulation, double-buffered uint4 loads.
__device__ __forceinline__ void sweep6h(
    const __half* __restrict__ Ebase, const __half2* __restrict__ vech,
    float* __restrict__ outv, int ibase, int nrows, int lane, float scaleMul)
{
    float acc[6] = {0.f, 0.f, 0.f, 0.f, 0.f, 0.f};
    const __half* base = Ebase + (size_t)ibase * ESTRIDE;

    if (nrows == 6) {
        uint4 cur[6];
        int c = lane;
#pragma unroll
        for (int r = 0; r < 6; r++)
            cur[r] = *(const uint4*)(base + (size_t)r * ESTRIDE + c * 8);
        for (;;) {
            int cn = c + 32;
            bool has = (cn < 188);
            uint4 nxt[6];
            if (has) {
#pragma unroll
                for (int r = 0; r < 6; r++)
                    nxt[r] = *(const uint4*)(base + (size_t)r * ESTRIDE + cn * 8);
            }
            uint4 wv = *(const uint4*)&vech[c * 4];
            __half2 w01 = *(const __half2*)&wv.x;
            __half2 w23 = *(const __half2*)&wv.y;
            __half2 w45 = *(const __half2*)&wv.z;
            __half2 w67 = *(const __half2*)&wv.w;
#pragma unroll
            for (int r = 0; r < 6; r++) {
                __half2 p = __hmul2(*(const __half2*)&cur[r].x, w01);
                p = __hfma2(*(const __half2*)&cur[r].y, w23, p);
                p = __hfma2(*(const __half2*)&cur[r].z, w45, p);
                p = __hfma2(*(const __half2*)&cur[r].w, w67, p);
                float2 pf = __half22float2(p);
                acc[r] += pf.x + pf.y;
            }
            if (!has) break;
#pragma unroll
            for (int r = 0; r < 6; r++) cur[r] = nxt[r];
            c = cn;
        }
    } else {
        for (int c = lane; c < 188; c += 32) {
            uint4 wv = *(const uint4*)&vech[c * 4];
            __half2 w01 = *(const __half2*)&wv.x;
            __half2 w23 = *(const __half2*)&wv.y;
            __half2 w45 = *(const __half2*)&wv.z;
            __half2 w67 = *(const __half2*)&wv.w;
            const __half* p0 = base + c * 8;
            for (int r = 0; r < nrows; r++) {
                uint4 ev = *(const uint4*)(p0 + (size_t)r * ESTRIDE);
                __half2 p = __hmul2(*(const __half2*)&ev.x, w01);
                p = __hfma2(*(const __half2*)&ev.y, w23, p);
                p = __hfma2(*(const __half2*)&ev.z, w45, p);
                p = __hfma2(*(const __half2*)&ev.w, w67, p);
                float2 pf = __half22float2(p);
                acc[r] += pf.x + pf.y;
            }
        }
    }

#pragma unroll
    for (int r = 0; r < 6; r++) {
        float s = acc[r];
#pragma unroll
        for (int o = 16; o; o >>= 1) s += __shfl_xor_sync(0xffffffffu, s, o);
        if (lane == 0 && r < nrows) {
            int i = ibase + r;
            float m = (i < 1500) ? (1.0f / 3000.0f) : 0.5f;
            __stcg(&outv[i], m * scaleMul / s);   // pad rows -> inf, never consumed
        }
    }
}

__global__ void __launch_bounds__(512) sinkhorn_pers()
{
    int b = blockIdx.x / CPB;
    int rank = blockIdx.x % CPB;
    int r0 = rank * RPC;
    int tid = threadIdx.x;
    int warp = tid >> 5, lane = tid & 31;

    int ibase = r0 + warp * 6;
    int nrows = max(0, min(6, r0 + RPC - ibase));   // warp 15 -> 4 rows

    __shared__ __align__(16) __half2 vech[752];

    const __half* Eb  = g_E16 + (size_t)b * EROWS * ESTRIDE;
    const __half* Etb = g_Et  + (size_t)b * EROWS * ESTRIDE;
    float* xb = g_x + b * EROWS;
    float* wb = g_w + b * EROWS;
    BatchBar* bar = &g_bar[b];

    if (tid < RPC) __stcg(&wb[r0 + tid], 1.0f);
    batch_barrier(bar, tid);

#pragma unroll 1
    for (int it = 0; it < ITERS_RUN; it++) {
        // ---- row phase: x = mu / (E w); w vector in half, scale 1 ----
        for (int t = tid; t < 752; t += 512) {
            int j = t * 2;
            float a = (j < MP1) ? __ldcg(&wb[j]) : 0.0f;
            float bb = (j + 1 < MP1) ? __ldcg(&wb[j + 1]) : 0.0f;
            vech[t] = __floats2half2_rn(a, bb);
        }
        __syncthreads();
        if (nrows > 0) sweep6h(Eb, vech, xb, ibase, nrows, lane, 1.0f);
        batch_barrier(bar, tid);

        // ---- col phase: w = nu / (Et x); x scaled by 2^22 for fp16 range ----
        for (int t = tid; t < 752; t += 512) {
            int j = t * 2;
            float a = (j < MP1) ? __ldcg(&xb[j]) * COLSCALE : 0.0f;
            float bb = (j + 1 < MP1) ? __ldcg(&xb[j + 1]) * COLSCALE : 0.0f;
            vech[t] = __floats2half2_rn(a, bb);
        }
        __syncthreads();
        if (nrows > 0) sweep6h(Etb, vech, wb, ibase, nrows, lane, COLSCALE);
        batch_barrier(bar, tid);
    }
}

// ---------------- final: out = E * x_i * w_j * 3000 ----------------
// grid (1501, 8), block 376; each thread handles 4 consecutive j
__global__ __launch_bounds__(384) void final_out(float* __restrict__ out)
{
    int i = blockIdx.x;
    int b = blockIdx.y;
    int j0 = threadIdx.x * 4;
    float xi = g_x[b * EROWS + i] * 3000.0f;
    const __half* erow = g_E16 + ((size_t)(b * EROWS + i)) * ESTRIDE;
    uint2 ev = *(const uint2*)(erow + j0);
    float4 wv = *(const float4*)&g_w[b * EROWS + j0];
    float2 e01 = __half22float2(*(const __half2*)&ev.x);
    float2 e23 = __half22float2(*(const __half2*)&ev.y);
    float* orow = out + ((size_t)(b * MP1 + i)) * 1501;
    float r0 = e01.x * xi * wv.x;
    float r1 = e01.y * xi * wv.y;
    float r2 = e23.x * xi * wv.z;
    float r3 = e23.y * xi * wv.w;
    if (j0 + 3 <= 1500) {
        orow[j0] = r0; orow[j0 + 1] = r1; orow[j0 + 2] = r2; orow[j0 + 3] = r3;
    } else {
        if (j0 <= 1500) orow[j0] = r0;
        if (j0 + 1 <= 1500) orow[j0 + 1] = r1;
        if (j0 + 2 <= 1500) orow[j0 + 2] = r2;
    }
}

// ---------------- launch ----------------
extern "C" void kernel_launch(void* const* d_in, const int* in_sizes, int n_in,
                              void* d_out, int out_size)
{
    const float* quer      = (const float*)d_in[0];
    const float* pos_start = (const float*)d_in[1];
    const float* pos_end   = (const float*)d_in[2];
    const float* W1 = (const float*)d_in[3];
    const float* b1 = (const float*)d_in[4];
    const float* W2 = (const float*)d_in[5];
    const float* b2 = (const float*)d_in[6];
    const float* W3 = (const float*)d_in[7];
    const float* b3 = (const float*)d_in[8];
    const float* binS = (const float*)d_in[9];

    __half *W1h, *W2h, *W3h, *tA, *tB, *F;
    cudaGetSymbolAddress((void**)&W1h, g_W1h);
    cudaGetSymbolAddress((void**)&W2h, g_W2h);
    cudaGetSymbolAddress((void**)&W3h, g_W3h);
    cudaGetSymbolAddress((void**)&tA, g_tA);
    cudaGetSymbolAddress((void**)&tB, g_tB);
    cudaGetSymbolAddress((void**)&F, g_F);

    prep_weights<<<512, 256>>>(W1, W2, W3);

    dim3 gG(188, 2);  // ceil(24000/128) x 256/128
    gemm16_l1<<<gG, 256>>>(quer, pos_end, pos_start, W1h, b1, tA);
    gemm16<<<gG, 256>>>(tA, W2h, b2, tB, MROWS, 256, 1);
    gemm16<<<gG, 256>>>(tB, W3h, b3, F,  MROWS, 256, 0);

    transposeF2<<<dim3(48, 8, 8), dim3(32, 8)>>>();
    scores16<<<dim3(12, 12, 8), 256>>>();
    fill_bins<<<dim3(6, 8), 256>>>(binS);

    sinkhorn_pers<<<BATCH * CPB, 512>>>();

    final_out<<<dim3(1501, 8), 376>>>((float*)d_out);
}